// round 3
// baseline (speedup 1.0000x reference)
#include <cuda_runtime.h>
#include <math.h>

#define R 32
#define V 50257
#define VR (V * R)           // 1,608,224 floats per i-slab
#define BATCH 1024
#define NSTEP 8
#define EPS 1e-10f

#define GATHER_BLOCKS 128    // 128 blocks * 8 warps = 1024 warps = 1 warp / batch row
#define RED_BX 40            // reduction blocks per i (40 * 32 = 1280 blocks)
#define THREADS 256

// Scratch (no allocation allowed in kernel_launch)
__device__ float g_M[R * R];
__device__ float g_pt[BATCH];

// ---------------------------------------------------------------------------
// Zero the M accumulator (atomics target). Must run every call (graph replay).
// ---------------------------------------------------------------------------
__global__ void tjd_init_kernel() {
    g_M[threadIdx.x] = 0.0f;
}

// ---------------------------------------------------------------------------
// Fused kernel:
//   blocks [0, GATHER_BLOCKS)            : per-row core-chain (prob_tilde)
//   blocks [GATHER_BLOCKS, +RED_BX*32)   : M = sum_v relu(core) reduction
// Both are independent until finalize, so they share one DRAM-bound wave.
// ---------------------------------------------------------------------------
__global__ __launch_bounds__(THREADS)
void tjd_main_kernel(const float* __restrict__ alpha,
                     const float* __restrict__ beta,
                     const float* __restrict__ core,
                     const int*   __restrict__ ids) {
    const int bid = blockIdx.x;

    if (bid < GATHER_BLOCKS) {
        // ---- gather/chain: one warp per batch row ----
        const int row  = bid * (THREADS / 32) + (threadIdx.x >> 5);
        const int lane = threadIdx.x & 31;
        const int* myids = ids + row * NSTEP;

        float v = fmaxf(alpha[lane], 0.0f) + EPS;   // lane holds v[lane]

        #pragma unroll 1
        for (int t = 0; t < NSTEP; t++) {
            const int id = myids[t];
            const float* base = core + (size_t)id * R + lane;
            // 32 independent loads (128B coalesced per i across the warp)
            float g[R];
            #pragma unroll
            for (int i = 0; i < R; i++)
                g[i] = __ldg(base + (size_t)i * VR);
            float nv = 0.0f;
            #pragma unroll
            for (int i = 0; i < R; i++)
                nv = fmaf(__shfl_sync(0xffffffffu, v, i),
                          fmaxf(g[i], 0.0f) + EPS, nv);
            v = nv;
        }

        float pt = v * (fmaxf(beta[lane], 0.0f) + EPS);
        #pragma unroll
        for (int o = 16; o; o >>= 1)
            pt += __shfl_xor_sync(0xffffffffu, pt, o);
        if (lane == 0) g_pt[row] = pt;
    } else {
        // ---- reduction: M[i][j] = sum_v relu(core[i,v,j]) ----
        const int rb = bid - GATHER_BLOCKS;
        const int i  = rb / RED_BX;          // which 6.4MB slab
        const int bx = rb % RED_BX;

        const float4* p = (const float4*)(core + (size_t)i * VR);
        const int n4 = VR / 4;               // 402,056 — exact, no tail

        // stride (RED_BX*THREADS) is a multiple of 8 float4s, so each thread's
        // 4 j-lanes are fixed: jb = (tid % 8) * 4
        float a0 = 0.f, a1 = 0.f, a2 = 0.f, a3 = 0.f;
        for (int idx = bx * THREADS + threadIdx.x; idx < n4;
             idx += RED_BX * THREADS) {
            float4 g = __ldg(p + idx);
            a0 += fmaxf(g.x, 0.0f);
            a1 += fmaxf(g.y, 0.0f);
            a2 += fmaxf(g.z, 0.0f);
            a3 += fmaxf(g.w, 0.0f);
        }

        __shared__ float sm[R];
        if (threadIdx.x < R) sm[threadIdx.x] = 0.0f;
        __syncthreads();
        const int jb = (threadIdx.x & 7) * 4;
        atomicAdd(&sm[jb + 0], a0);
        atomicAdd(&sm[jb + 1], a1);
        atomicAdd(&sm[jb + 2], a2);
        atomicAdd(&sm[jb + 3], a3);
        __syncthreads();
        if (threadIdx.x < R)
            atomicAdd(&g_M[i * R + threadIdx.x], sm[threadIdx.x]);
    }
}

// ---------------------------------------------------------------------------
// Finalize: z = a (M+V*eps)^8 b ; prob = pt/z ; loss = -mean(log(prob+eps))
// Single block, 1024 threads (one per batch row).
// ---------------------------------------------------------------------------
__global__ __launch_bounds__(BATCH)
void tjd_finalize_kernel(const float* __restrict__ alpha,
                         const float* __restrict__ beta,
                         float* __restrict__ out, int out_size) {
    __shared__ float sM[R * R];
    __shared__ float red[BATCH];
    __shared__ float szs;

    const int t = threadIdx.x;
    sM[t] = g_M[t] + (float)V * EPS;   // fold the per-element eps back in
    __syncthreads();

    if (t < R) {
        float u = fmaxf(alpha[t], 0.0f) + EPS;
        #pragma unroll 1
        for (int s = 0; s < NSTEP; s++) {
            float nu = 0.0f;
            #pragma unroll
            for (int i = 0; i < R; i++)
                nu = fmaf(__shfl_sync(0xffffffffu, u, i), sM[i * R + t], nu);
            u = nu;                     // overflows to +inf ~step 7, as fp32 ref does
        }
        float z = u * (fmaxf(beta[t], 0.0f) + EPS);
        #pragma unroll
        for (int o = 16; o; o >>= 1)
            z += __shfl_xor_sync(0xffffffffu, z, o);
        if (t == 0) szs = z;
    }
    __syncthreads();

    const float z = szs;
    const float prob = g_pt[t] / z;     // finite/inf -> 0, matching reference

    if (out_size >= BATCH + 1)      out[1 + t] = prob;   // [loss, prob...]
    else if (out_size == BATCH)     out[t]     = prob;   // prob only

    red[t] = -logf(prob + EPS);
    __syncthreads();
    #pragma unroll
    for (int s = BATCH / 2; s > 0; s >>= 1) {
        if (t < s) red[t] += red[t + s];
        __syncthreads();
    }
    if (t == 0) {
        const float loss = red[0] / (float)BATCH;
        if (out_size != BATCH) out[0] = loss;            // 1025 or loss-only
    }
}

// ---------------------------------------------------------------------------
extern "C" void kernel_launch(void* const* d_in, const int* in_sizes, int n_in,
                              void* d_out, int out_size) {
    const float* alpha = (const float*)d_in[0];   // (32,)
    const float* beta  = (const float*)d_in[1];   // (32,)
    const float* core  = (const float*)d_in[2];   // (32, 50257, 32)
    const int*   ids   = (const int*)  d_in[3];   // (1024, 8)
    float* out = (float*)d_out;

    tjd_init_kernel<<<1, R * R>>>();
    tjd_main_kernel<<<GATHER_BLOCKS + RED_BX * R, THREADS>>>(alpha, beta, core, ids);
    tjd_finalize_kernel<<<1, BATCH>>>(alpha, beta, out, out_size);
}